// round 3
// baseline (speedup 1.0000x reference)
#include <cuda_runtime.h>
#include <cuda_bf16.h>

// SurvLoss via monotonicity: log(cumsum(exp)) is increasing, so
// segment_max = value at LAST occurrence index of each segment.
//
// K1 (single streaming pass, minimal non-load work):
//   - per-thread exp sums -> one block reduce -> g_block_agg
//   - per-segment last index (smem filter + smem atomicMax, reverse order)
//   - per-segment E-counts via GLOBAL RED.ADD (no smem histogram)
//   - sum(outs*E), sum(E) in registers
// K2: 1-block double exclusive scan of block sums -> g_block_prefix
// K3: warp-per-segment: recompute within-block partial exp-sum from outs
//     (L2-hot), y = max(log(total),0), loss = (sum y*cnt - s1)/obs.
//     Resets all device state for the next graph replay.

#define NUM_TIMES 1024
#define NBLK      1024
#define THREADS   256
#define CHUNKS    16
#define TILE      16384                     // elements per block

__device__ float              g_block_agg[NBLK];
__device__ double             g_block_prefix[NBLK];
__device__ int                g_last[NUM_TIMES];      // 0 = empty, else idx+1
__device__ int                g_cnt[NUM_TIMES];
__device__ double             g_s1;
__device__ unsigned long long g_obs;
__device__ double             g_s2;
__device__ unsigned int       g_done;

// ---------------------------------------------------------------- K1
__global__ void __launch_bounds__(THREADS) k1_main(const float* __restrict__ outs,
                                                   const int* __restrict__ T_E,
                                                   const int* __restrict__ T_T) {
    __shared__ int   s_last[NUM_TIMES];
    __shared__ float wtot[8];
    __shared__ float rs1[8];
    __shared__ int   rob[8];

    const int b = blockIdx.x, tid = threadIdx.x;
    const int lane = tid & 31, w = tid >> 5;

    for (int i = tid; i < NUM_TIMES; i += THREADS) s_last[i] = 0;
    __syncthreads();

    const float4* o4 = (const float4*)outs;
    const int4*   e4 = (const int4*)T_E;
    const int4*   t4 = (const int4*)T_T;
    const int base4 = b * (TILE / 4);

    float thr_tot = 0.f;
    float ls1 = 0.f;
    int   lob = 0;

    // Reverse chunk order so the shared-mem last-occurrence filter kills
    // most atomicMax attempts (first hit per segment is the largest index).
#pragma unroll 4
    for (int c = CHUNKS - 1; c >= 0; --c) {
        const int fi = base4 + c * THREADS + tid;
        float4 v  = o4[fi];
        int4   tt = t4[fi];
        int4   te = e4[fi];

        thr_tot += __expf(v.x) + __expf(v.y) + __expf(v.z) + __expf(v.w);

        const int gi = fi * 4;

        // last-occurrence: smem filter + smem atomicMax (few fires)
        int sg3 = abs(tt.w); if (s_last[sg3] < gi + 4) atomicMax(&s_last[sg3], gi + 4);
        int sg2 = abs(tt.z); if (s_last[sg2] < gi + 3) atomicMax(&s_last[sg2], gi + 3);
        int sg1 = abs(tt.y); if (s_last[sg1] < gi + 2) atomicMax(&s_last[sg1], gi + 2);
        int sg0 = abs(tt.x); if (s_last[sg0] < gi + 1) atomicMax(&s_last[sg0], gi + 1);

        // E-counts: global RED.ADD (L2 atomic ALUs, overlaps with DRAM traffic)
        if (te.x > 0) atomicAdd(&g_cnt[sg0], 1);
        if (te.y > 0) atomicAdd(&g_cnt[sg1], 1);
        if (te.z > 0) atomicAdd(&g_cnt[sg2], 1);
        if (te.w > 0) atomicAdd(&g_cnt[sg3], 1);

        // branchless s1 / obs
        ls1 += (te.x > 0) ? v.x : 0.f;
        ls1 += (te.y > 0) ? v.y : 0.f;
        ls1 += (te.z > 0) ? v.z : 0.f;
        ls1 += (te.w > 0) ? v.w : 0.f;
        lob += (te.x > 0) + (te.y > 0) + (te.z > 0) + (te.w > 0);
    }

    // block reductions: exp total, s1, obs
    float xx = thr_tot;
#pragma unroll
    for (int o = 16; o; o >>= 1) {
        xx  += __shfl_xor_sync(0xffffffffu, xx, o);
        ls1 += __shfl_xor_sync(0xffffffffu, ls1, o);
        lob += __shfl_xor_sync(0xffffffffu, lob, o);
    }
    if (lane == 0) { wtot[w] = xx; rs1[w] = ls1; rob[w] = lob; }
    __syncthreads();
    if (tid == 0) {
        float bt = 0.f, bs = 0.f; int bo = 0;
#pragma unroll
        for (int k = 0; k < 8; k++) { bt += wtot[k]; bs += rs1[k]; bo += rob[k]; }
        g_block_agg[b] = bt;
        atomicAdd(&g_s1, (double)bs);
        atomicAdd(&g_obs, (unsigned long long)bo);
    }

    // flush last-occurrence table to global
    __syncthreads();
    for (int i = tid; i < NUM_TIMES; i += THREADS) {
        int m = s_last[i];
        if (m) atomicMax(&g_last[i], m);
    }
}

// ---------------------------------------------------------------- K2
__global__ void __launch_bounds__(1024) k2_scan() {
    const int tid = threadIdx.x;
    const int lane = tid & 31, w = tid >> 5;

    double v = (double)g_block_agg[tid];
    double x = v;
#pragma unroll
    for (int o = 1; o < 32; o <<= 1) {
        double y = __shfl_up_sync(0xffffffffu, x, o);
        if (lane >= o) x += y;
    }
    __shared__ double wsum[32];
    if (lane == 31) wsum[w] = x;
    __syncthreads();
    if (w == 0) {
        double t = wsum[lane];
#pragma unroll
        for (int o = 1; o < 32; o <<= 1) {
            double y = __shfl_up_sync(0xffffffffu, t, o);
            if (lane >= o) t += y;
        }
        wsum[lane] = t;
    }
    __syncthreads();
    double wexcl = (w == 0) ? 0.0 : wsum[w - 1];
    g_block_prefix[tid] = wexcl + (x - v);   // exclusive prefix for block tid
}

// ---------------------------------------------------------------- K3
// 128 blocks x 256 threads = 1024 warps; warp t handles segment t.
// Recomputes the within-block partial exp-sum directly from outs (L2-hot).
__global__ void __launch_bounds__(THREADS) k3_finalize(const float* __restrict__ outs,
                                                       float* __restrict__ out) {
    const int tid = threadIdx.x;
    const int lane = tid & 31, w = tid >> 5;
    const int t = blockIdx.x * 8 + w;

    int e = 0, cnt = 0;
    if (lane == 0) {
        e   = g_last[t];
        cnt = g_cnt[t];
        g_last[t] = 0;      // reset for next graph replay
        g_cnt[t]  = 0;
    }
    e   = __shfl_sync(0xffffffffu, e, 0);
    cnt = __shfl_sync(0xffffffffu, cnt, 0);

    double contrib = 0.0;
    if (e > 0 && cnt > 0) {
        const int idx = e - 1;
        const int b   = idx >> 14;          // block that contains idx
        const int r   = idx & 16383;        // offset within block
        const int ql  = r >> 2;             // last float4 index
        const int rem = r & 3;              // components of last float4 included

        const float4* o4 = (const float4*)outs + b * (TILE / 4);
        double acc = 0.0;
        for (int q = lane; q <= ql; q += 32) {
            float4 v = o4[q];
            float s;
            if (q < ql) {
                s = __expf(v.x) + __expf(v.y) + __expf(v.z) + __expf(v.w);
            } else {
                s = __expf(v.x);
                if (rem >= 1) s += __expf(v.y);
                if (rem >= 2) s += __expf(v.z);
                if (rem >= 3) s += __expf(v.w);
            }
            acc += (double)s;
        }
#pragma unroll
        for (int o = 16; o; o >>= 1) acc += __shfl_xor_sync(0xffffffffu, acc, o);

        if (lane == 0) {
            double total = g_block_prefix[b] + acc;
            double y = log(total);
            if (y < 0.0) y = 0.0;
            contrib = y * (double)cnt;
        }
    }

    __shared__ double cs[8];
    if (lane == 0) cs[w] = contrib;
    __syncthreads();
    if (tid == 0) {
        double s = 0.0;
#pragma unroll
        for (int k = 0; k < 8; k++) s += cs[k];
        atomicAdd(&g_s2, s);
        __threadfence();
        unsigned int old = atomicAdd(&g_done, 1u);
        if (old == 127u) {
            double s2 = atomicAdd(&g_s2, 0.0);   // coherent read
            double loss = (s2 - g_s1) / (double)g_obs;
            out[0] = (float)loss;
            g_s2 = 0.0; g_s1 = 0.0; g_obs = 0ull; g_done = 0u;
        }
    }
}

// ---------------------------------------------------------------- launch
extern "C" void kernel_launch(void* const* d_in, const int* in_sizes, int n_in,
                              void* d_out, int out_size) {
    const float* outs = (const float*)d_in[0];
    const int*   T_E  = (const int*)d_in[1];
    const int*   T_T  = (const int*)d_in[2];
    float* out = (float*)d_out;

    k1_main<<<NBLK, THREADS>>>(outs, T_E, T_T);
    k2_scan<<<1, 1024>>>();
    k3_finalize<<<128, THREADS>>>(outs, out);
}

// round 4
// speedup vs baseline: 8.8491x; 8.8491x over previous
#include <cuda_runtime.h>
#include <cuda_bf16.h>

// SurvLoss. Monotonicity: log(cumsum(exp)) is increasing => segment_max is the
// value at the LAST occurrence index of each segment. And
// sum_t segmax_t*cnt_t == sum_i E_i * ymax[seg_i]  => no histogram needed.
//
// K1: stream outs/T_E/T_T once: span sums of exp, block sums, s1/obs,
//     last-occurrence (smem filter + rare atomicMax), packed (seg,E) u16 array.
//     Last-done block scans the 1024 block sums (double, exclusive).
// K2: warp-per-segment ymax from span sums + one partial float4. Resets g_last.
// K3: gather pass over packed array: s2 = sum E*ymax[seg]; finalize + resets.

#define NUM_TIMES 1024
#define NBLK      1024
#define THREADS   256
#define CHUNKS    16
#define TILE      16384
#define SPANS     128

__device__ float              g_wc[NBLK * SPANS];     // 128-elem span sums of exp
__device__ float              g_block_agg[NBLK];
__device__ double             g_block_prefix[NBLK];
__device__ int                g_last[NUM_TIMES];      // 0 = empty, else idx+1
__device__ float              g_ymax[NUM_TIMES];
__device__ uint2              g_packed[NBLK * TILE / 4];  // 4 x u16 per uint2
__device__ double             g_s1;
__device__ unsigned long long g_obs;
__device__ double             g_s2;
__device__ unsigned int       g_done1;
__device__ unsigned int       g_done2;

// ---------------------------------------------------------------- K1
__global__ void __launch_bounds__(THREADS) k1_main(const float* __restrict__ outs,
                                                   const int* __restrict__ T_E,
                                                   const int* __restrict__ T_T) {
    __shared__ int   s_last[NUM_TIMES];
    __shared__ float wtot[8];
    __shared__ float rs1[8];
    __shared__ int   rob[8];
    __shared__ unsigned int s_islast;

    const int b = blockIdx.x, tid = threadIdx.x;
    const int lane = tid & 31, w = tid >> 5;

    for (int i = tid; i < NUM_TIMES; i += THREADS) s_last[i] = 0;
    __syncthreads();

    const float4* o4 = (const float4*)outs;
    const int4*   e4 = (const int4*)T_E;
    const int4*   t4 = (const int4*)T_T;
    const int base4 = b * (TILE / 4);

    float thr_tot = 0.f;
    float ls1 = 0.f;
    int   lob = 0;

    // Reverse chunk order: the smem filter kills most atomicMax attempts.
#pragma unroll 4
    for (int c = CHUNKS - 1; c >= 0; --c) {
        const int fi = base4 + c * THREADS + tid;
        float4 v  = o4[fi];
        int4   tt = t4[fi];
        int4   te = e4[fi];

        float s = __expf(v.x) + __expf(v.y) + __expf(v.z) + __expf(v.w);
        thr_tot += s;

        // span sum (warp w of chunk c covers 128 contiguous elements)
        float x = s;
#pragma unroll
        for (int o = 16; o; o >>= 1) x += __shfl_xor_sync(0xffffffffu, x, o);
        if (lane == 0) g_wc[b * SPANS + c * 8 + w] = x;

        const int gi = fi * 4;
        int sg0 = abs(tt.x), sg1 = abs(tt.y), sg2 = abs(tt.z), sg3 = abs(tt.w);

        // last-occurrence: cheap LDS filter, rare smem atomicMax
        if (s_last[sg3] < gi + 4) atomicMax(&s_last[sg3], gi + 4);
        if (s_last[sg2] < gi + 3) atomicMax(&s_last[sg2], gi + 3);
        if (s_last[sg1] < gi + 2) atomicMax(&s_last[sg1], gi + 2);
        if (s_last[sg0] < gi + 1) atomicMax(&s_last[sg0], gi + 1);

        // packed (seg<<1)|E  -> 4 x u16 in one uint2 store
        unsigned int p0 = ((unsigned)sg0 << 1) | (te.x > 0);
        unsigned int p1 = ((unsigned)sg1 << 1) | (te.y > 0);
        unsigned int p2 = ((unsigned)sg2 << 1) | (te.z > 0);
        unsigned int p3 = ((unsigned)sg3 << 1) | (te.w > 0);
        uint2 pk;
        pk.x = p0 | (p1 << 16);
        pk.y = p2 | (p3 << 16);
        g_packed[fi] = pk;

        // branchless s1 / obs
        ls1 += (te.x > 0) ? v.x : 0.f;
        ls1 += (te.y > 0) ? v.y : 0.f;
        ls1 += (te.z > 0) ? v.z : 0.f;
        ls1 += (te.w > 0) ? v.w : 0.f;
        lob += (te.x > 0) + (te.y > 0) + (te.z > 0) + (te.w > 0);
    }

    // block reductions
    float xx = thr_tot;
#pragma unroll
    for (int o = 16; o; o >>= 1) {
        xx  += __shfl_xor_sync(0xffffffffu, xx, o);
        ls1 += __shfl_xor_sync(0xffffffffu, ls1, o);
        lob += __shfl_xor_sync(0xffffffffu, lob, o);
    }
    if (lane == 0) { wtot[w] = xx; rs1[w] = ls1; rob[w] = lob; }
    __syncthreads();
    if (tid == 0) {
        float bt = 0.f, bs = 0.f; int bo = 0;
#pragma unroll
        for (int k = 0; k < 8; k++) { bt += wtot[k]; bs += rs1[k]; bo += rob[k]; }
        g_block_agg[b] = bt;
        atomicAdd(&g_s1, (double)bs);
        atomicAdd(&g_obs, (unsigned long long)bo);
    }

    // flush last-occurrence table
    __syncthreads();
    for (int i = tid; i < NUM_TIMES; i += THREADS) {
        int m = s_last[i];
        if (m) atomicMax(&g_last[i], m);
    }
    __syncthreads();

    // last-done block performs the exclusive scan of the 1024 block sums
    if (tid == 0) {
        __threadfence();
        s_islast = (atomicAdd(&g_done1, 1u) == NBLK - 1u);
    }
    __syncthreads();
    if (s_islast) {
        // 256 threads, 4 values each
        double v0 = (double)__ldcg(&g_block_agg[4 * tid + 0]);
        double v1 = (double)__ldcg(&g_block_agg[4 * tid + 1]);
        double v2 = (double)__ldcg(&g_block_agg[4 * tid + 2]);
        double v3 = (double)__ldcg(&g_block_agg[4 * tid + 3]);
        double c0 = v0, c1 = c0 + v1, c2 = c1 + v2, c3 = c2 + v3;

        double x = c3;
#pragma unroll
        for (int o = 1; o < 32; o <<= 1) {
            double y = __shfl_up_sync(0xffffffffu, x, o);
            if (lane >= o) x += y;
        }
        __shared__ double wsc[8];
        if (lane == 31) wsc[w] = x;
        __syncthreads();
        double wexcl = 0.0;
#pragma unroll
        for (int k = 0; k < 8; k++) if (k < w) wexcl += wsc[k];
        double excl = wexcl + (x - c3);

        g_block_prefix[4 * tid + 0] = excl;
        g_block_prefix[4 * tid + 1] = excl + c0;
        g_block_prefix[4 * tid + 2] = excl + c1;
        g_block_prefix[4 * tid + 3] = excl + c2;
        if (tid == 0) g_done1 = 0;
    }
}

// ---------------------------------------------------------------- K2
// 128 blocks x 256 threads = 1024 warps; warp t handles segment t.
__global__ void __launch_bounds__(THREADS) k2_ymax(const float* __restrict__ outs) {
    const int tid = threadIdx.x;
    const int lane = tid & 31, w = tid >> 5;
    const int t = blockIdx.x * 8 + w;

    int e = 0;
    if (lane == 0) {
        e = g_last[t];
        g_last[t] = 0;          // reset for next graph replay
    }
    e = __shfl_sync(0xffffffffu, e, 0);

    float ym = 0.f;
    if (e > 0) {
        const int idx = e - 1;
        const int b   = idx >> 14;
        const int r   = idx & 16383;
        const int sh  = r >> 7;      // span within block
        const int off = r & 127;     // last included element within span

        double acc = 0.0;
        for (int s = lane; s < sh; s += 32) acc += (double)g_wc[b * SPANS + s];

        const float4* o4 = (const float4*)outs;
        float4 v = o4[b * (TILE / 4) + sh * 32 + lane];
        const int e0 = lane * 4;
        if (e0     <= off) acc += (double)__expf(v.x);
        if (e0 + 1 <= off) acc += (double)__expf(v.y);
        if (e0 + 2 <= off) acc += (double)__expf(v.z);
        if (e0 + 3 <= off) acc += (double)__expf(v.w);

#pragma unroll
        for (int o = 16; o; o >>= 1) acc += __shfl_xor_sync(0xffffffffu, acc, o);

        if (lane == 0) {
            double total = g_block_prefix[b] + acc;
            double y = log(total);
            ym = (y < 0.0) ? 0.f : (float)y;
        }
    }
    if (lane == 0) g_ymax[t] = ym;
}

// ---------------------------------------------------------------- K3
// s2 = sum_i E_i * ymax[seg_i] via smem gather over the packed array.
__global__ void __launch_bounds__(THREADS) k3_s2(float* __restrict__ out) {
    __shared__ float sy[NUM_TIMES];
    __shared__ double cs[8];

    const int b = blockIdx.x, tid = threadIdx.x;
    const int lane = tid & 31, w = tid >> 5;

    for (int i = tid; i < NUM_TIMES; i += THREADS) sy[i] = g_ymax[i];
    __syncthreads();

    const int base4 = b * (TILE / 4);
    float s2 = 0.f;
#pragma unroll 4
    for (int c = 0; c < CHUNKS; c++) {
        uint2 pk = g_packed[base4 + c * THREADS + tid];
        unsigned int a0 = pk.x & 0xffffu, a1 = pk.x >> 16;
        unsigned int a2 = pk.y & 0xffffu, a3 = pk.y >> 16;
        float v0 = sy[a0 >> 1];
        float v1 = sy[a1 >> 1];
        float v2 = sy[a2 >> 1];
        float v3 = sy[a3 >> 1];
        s2 += (a0 & 1) ? v0 : 0.f;
        s2 += (a1 & 1) ? v1 : 0.f;
        s2 += (a2 & 1) ? v2 : 0.f;
        s2 += (a3 & 1) ? v3 : 0.f;
    }

    double d = (double)s2;
#pragma unroll
    for (int o = 16; o; o >>= 1) d += __shfl_xor_sync(0xffffffffu, d, o);
    if (lane == 0) cs[w] = d;
    __syncthreads();
    if (tid == 0) {
        double s = 0.0;
#pragma unroll
        for (int k = 0; k < 8; k++) s += cs[k];
        atomicAdd(&g_s2, s);
        __threadfence();
        unsigned int old = atomicAdd(&g_done2, 1u);
        if (old == NBLK - 1u) {
            double s2t = atomicAdd(&g_s2, 0.0);
            double s1t = atomicAdd(&g_s1, 0.0);
            unsigned long long obs = atomicAdd(&g_obs, 0ull);
            out[0] = (float)((s2t - s1t) / (double)obs);
            g_s2 = 0.0; g_s1 = 0.0; g_obs = 0ull; g_done2 = 0u;
        }
    }
}

// ---------------------------------------------------------------- launch
extern "C" void kernel_launch(void* const* d_in, const int* in_sizes, int n_in,
                              void* d_out, int out_size) {
    const float* outs = (const float*)d_in[0];
    const int*   T_E  = (const int*)d_in[1];
    const int*   T_T  = (const int*)d_in[2];
    float* out = (float*)d_out;

    k1_main<<<NBLK, THREADS>>>(outs, T_E, T_T);
    k2_ymax<<<128, THREADS>>>(outs);
    k3_s2<<<NBLK, THREADS>>>(out);
}

// round 5
// speedup vs baseline: 9.7867x; 1.1060x over previous
#include <cuda_runtime.h>
#include <cuda_bf16.h>

// SurvLoss. log(cumsum(exp)) is monotone => segment_max = value at the LAST
// occurrence index of each segment; loss_s2 = sum_t ymax_t * cnt_t.
//
// K1: one pass over 192MB. Warp w of block b owns contiguous elems
//     [b*16384 + w*2048, +2048), so its register exp-sum is a span sum.
//     smem: last-occurrence filter+atomicMax, count histogram. Last-done
//     block scans the 1024 block sums (double, exclusive).
// K2: warp-per-segment: prefix = block_prefix + warp sums before region +
//     partial recompute (<=2048 elems, L2-hot); contrib = max(log,0)*cnt.
//     Done-counter finalize; resets all state for graph replay.

#define NUM_TIMES 1024
#define NBLK      1024
#define THREADS   256
#define ITERS     16
#define TILE      16384

__device__ float              g_wsum[NBLK * 8];       // per-warp (2048-elem) exp sums
__device__ float              g_block_agg[NBLK];
__device__ double             g_block_prefix[NBLK];
__device__ int                g_last[NUM_TIMES];      // 0 = empty, else idx+1
__device__ int                g_cnt[NUM_TIMES];
__device__ double             g_s1;
__device__ unsigned long long g_obs;
__device__ double             g_s2;
__device__ unsigned int       g_done1;
__device__ unsigned int       g_done2;

// ---------------------------------------------------------------- K1
__global__ void __launch_bounds__(THREADS) k1_main(const float* __restrict__ outs,
                                                   const int* __restrict__ T_E,
                                                   const int* __restrict__ T_T) {
    __shared__ int   s_last[NUM_TIMES];
    __shared__ int   s_cnt[NUM_TIMES];
    __shared__ float wtot[8];
    __shared__ float rs1[8];
    __shared__ int   rob[8];
    __shared__ unsigned int s_islast;

    const int b = blockIdx.x, tid = threadIdx.x;
    const int lane = tid & 31, w = tid >> 5;

    for (int i = tid; i < NUM_TIMES; i += THREADS) { s_last[i] = 0; s_cnt[i] = 0; }
    __syncthreads();

    const float4* o4 = (const float4*)outs;
    const int4*   e4 = (const int4*)T_E;
    const int4*   t4 = (const int4*)T_T;
    // warp w owns contiguous float4s [b*4096 + w*512, +512)
    const int wbase = b * (TILE / 4) + w * 512;

    float thr_tot = 0.f;
    float ls1 = 0.f;
    int   lob = 0;

    // Reverse order: smem filter kills most atomicMax attempts.
#pragma unroll 4
    for (int c = ITERS - 1; c >= 0; --c) {
        const int fi = wbase + c * 32 + lane;
        float4 v  = o4[fi];
        int4   tt = t4[fi];
        int4   te = e4[fi];

        thr_tot += __expf(v.x) + __expf(v.y) + __expf(v.z) + __expf(v.w);

        const int gi = fi * 4;
        int sg0 = abs(tt.x), sg1 = abs(tt.y), sg2 = abs(tt.z), sg3 = abs(tt.w);

        // last-occurrence: LDS filter, rare smem atomicMax
        if (s_last[sg3] < gi + 4) atomicMax(&s_last[sg3], gi + 4);
        if (s_last[sg2] < gi + 3) atomicMax(&s_last[sg2], gi + 3);
        if (s_last[sg1] < gi + 2) atomicMax(&s_last[sg1], gi + 2);
        if (s_last[sg0] < gi + 1) atomicMax(&s_last[sg0], gi + 1);

        // count histogram (E is 0/1)
        if (te.x) atomicAdd(&s_cnt[sg0], 1);
        if (te.y) atomicAdd(&s_cnt[sg1], 1);
        if (te.z) atomicAdd(&s_cnt[sg2], 1);
        if (te.w) atomicAdd(&s_cnt[sg3], 1);

        ls1 += te.x ? v.x : 0.f;
        ls1 += te.y ? v.y : 0.f;
        ls1 += te.z ? v.z : 0.f;
        ls1 += te.w ? v.w : 0.f;
        lob += te.x + te.y + te.z + te.w;
    }

    // warp reduce: exp region sum (contiguous span!), s1, obs
    float xx = thr_tot;
#pragma unroll
    for (int o = 16; o; o >>= 1) {
        xx  += __shfl_xor_sync(0xffffffffu, xx, o);
        ls1 += __shfl_xor_sync(0xffffffffu, ls1, o);
        lob += __shfl_xor_sync(0xffffffffu, lob, o);
    }
    if (lane == 0) {
        g_wsum[b * 8 + w] = xx;
        wtot[w] = xx; rs1[w] = ls1; rob[w] = lob;
    }
    __syncthreads();
    if (tid == 0) {
        float bt = 0.f, bs = 0.f; int bo = 0;
#pragma unroll
        for (int k = 0; k < 8; k++) { bt += wtot[k]; bs += rs1[k]; bo += rob[k]; }
        g_block_agg[b] = bt;
        atomicAdd(&g_s1, (double)bs);
        atomicAdd(&g_obs, (unsigned long long)bo);
    }

    // flush segment tables
    __syncthreads();
    for (int i = tid; i < NUM_TIMES; i += THREADS) {
        int m = s_last[i];
        if (m) atomicMax(&g_last[i], m);
        int cnt = s_cnt[i];
        if (cnt) atomicAdd(&g_cnt[i], cnt);
    }
    __syncthreads();

    // last-done block: exclusive double scan of the 1024 block sums
    if (tid == 0) {
        __threadfence();
        s_islast = (atomicAdd(&g_done1, 1u) == NBLK - 1u);
    }
    __syncthreads();
    if (s_islast) {
        double v0 = (double)__ldcg(&g_block_agg[4 * tid + 0]);
        double v1 = (double)__ldcg(&g_block_agg[4 * tid + 1]);
        double v2 = (double)__ldcg(&g_block_agg[4 * tid + 2]);
        double v3 = (double)__ldcg(&g_block_agg[4 * tid + 3]);
        double c0 = v0, c1 = c0 + v1, c2 = c1 + v2, c3 = c2 + v3;

        double x = c3;
#pragma unroll
        for (int o = 1; o < 32; o <<= 1) {
            double y = __shfl_up_sync(0xffffffffu, x, o);
            if (lane >= o) x += y;
        }
        __shared__ double wsc[8];
        if (lane == 31) wsc[w] = x;
        __syncthreads();
        double wexcl = 0.0;
#pragma unroll
        for (int k = 0; k < 8; k++) if (k < w) wexcl += wsc[k];
        double excl = wexcl + (x - c3);

        g_block_prefix[4 * tid + 0] = excl;
        g_block_prefix[4 * tid + 1] = excl + c0;
        g_block_prefix[4 * tid + 2] = excl + c1;
        g_block_prefix[4 * tid + 3] = excl + c2;
        if (tid == 0) g_done1 = 0;
    }
}

// ---------------------------------------------------------------- K2
// 128 blocks x 256 threads = 1024 warps; warp t handles segment t.
__global__ void __launch_bounds__(THREADS) k2_finalize(const float* __restrict__ outs,
                                                       float* __restrict__ out) {
    const int tid = threadIdx.x;
    const int lane = tid & 31, w = tid >> 5;
    const int t = blockIdx.x * 8 + w;

    int e = 0, cnt = 0;
    if (lane == 0) {
        e   = g_last[t];
        cnt = g_cnt[t];
        g_last[t] = 0;      // reset for next graph replay
        g_cnt[t]  = 0;
    }
    e   = __shfl_sync(0xffffffffu, e, 0);
    cnt = __shfl_sync(0xffffffffu, cnt, 0);

    double contrib = 0.0;
    if (e > 0 && cnt > 0) {
        const int idx = e - 1;
        const int b   = idx >> 14;           // block
        const int wr  = (idx >> 11) & 7;     // warp-region within block
        const int r   = idx & 2047;          // offset within region (last incl.)
        const int ql  = r >> 2;              // last float4 index within region
        const int rem = r & 3;

        double acc = 0.0;
        if (lane < wr) acc = (double)g_wsum[b * 8 + lane];   // regions before

        const float4* o4 = (const float4*)outs + b * (TILE / 4) + wr * 512;
        for (int q = lane; q <= ql; q += 32) {
            float4 v = o4[q];
            float s;
            if (q < ql) {
                s = __expf(v.x) + __expf(v.y) + __expf(v.z) + __expf(v.w);
            } else {
                s = __expf(v.x);
                if (rem >= 1) s += __expf(v.y);
                if (rem >= 2) s += __expf(v.z);
                if (rem >= 3) s += __expf(v.w);
            }
            acc += (double)s;
        }
#pragma unroll
        for (int o = 16; o; o >>= 1) acc += __shfl_xor_sync(0xffffffffu, acc, o);

        if (lane == 0) {
            double total = g_block_prefix[b] + acc;
            double y = log(total);
            if (y < 0.0) y = 0.0;
            contrib = y * (double)cnt;
        }
    }

    __shared__ double cs[8];
    if (lane == 0) cs[w] = contrib;
    __syncthreads();
    if (tid == 0) {
        double s = 0.0;
#pragma unroll
        for (int k = 0; k < 8; k++) s += cs[k];
        atomicAdd(&g_s2, s);
        __threadfence();
        unsigned int old = atomicAdd(&g_done2, 1u);
        if (old == 127u) {
            double s2t = atomicAdd(&g_s2, 0.0);
            double s1t = atomicAdd(&g_s1, 0.0);
            unsigned long long obs = atomicAdd(&g_obs, 0ull);
            out[0] = (float)((s2t - s1t) / (double)obs);
            g_s2 = 0.0; g_s1 = 0.0; g_obs = 0ull; g_done2 = 0u;
        }
    }
}

// ---------------------------------------------------------------- launch
extern "C" void kernel_launch(void* const* d_in, const int* in_sizes, int n_in,
                              void* d_out, int out_size) {
    const float* outs = (const float*)d_in[0];
    const int*   T_E  = (const int*)d_in[1];
    const int*   T_T  = (const int*)d_in[2];
    float* out = (float*)d_out;

    k1_main<<<NBLK, THREADS>>>(outs, T_E, T_T);
    k2_finalize<<<128, THREADS>>>(outs, out);
}